// round 11
// baseline (speedup 1.0000x reference)
#include <cuda_runtime.h>
#include <stdint.h>

// PinPos forward: pin position = node position + pin offset (theta == 0).
// pos = [x_0..x_{N-1}, y_0..y_{N-1}]  (2N floats)
// out = [pinx_0..pinx_{P-1}, piny_0..piny_{P-1}]  (2P floats)
//
// NOTE: JAX default config has x64 disabled, so the "int64" maps in the
// reference are actually int32 on the wire. Reading them as long long was
// the cause of the round-5 illegal memory access.
//
// HBM-bound: stream offx/offy/p2n/out fully coalesced (vec4), gather pos
// through L2 (pos is 16 MB -> fully L2-resident, 126 MB L2).

__global__ __launch_bounds__(256)
void pinpos_kernel(const float* __restrict__ pos,
                   const float* __restrict__ offx,
                   const float* __restrict__ offy,
                   const int* __restrict__ p2n,
                   float* __restrict__ out,
                   int num_pins, int num_nodes)
{
    const float* __restrict__ pos_y = pos + num_nodes;
    float* __restrict__ out_y = out + num_pins;

    int i = (blockIdx.x * blockDim.x + threadIdx.x) * 4;

    if (i + 3 < num_pins) {
        // Front-batch all streaming loads (3x16B) -> high MLP
        float4 ox = *reinterpret_cast<const float4*>(offx + i);
        float4 oy = *reinterpret_cast<const float4*>(offy + i);
        int4   n  = *reinterpret_cast<const int4*>(p2n + i);

        // Gathers: pos is 16 MB, L2-resident after warmup
        float px0 = __ldg(pos   + n.x);
        float px1 = __ldg(pos   + n.y);
        float px2 = __ldg(pos   + n.z);
        float px3 = __ldg(pos   + n.w);
        float py0 = __ldg(pos_y + n.x);
        float py1 = __ldg(pos_y + n.y);
        float py2 = __ldg(pos_y + n.z);
        float py3 = __ldg(pos_y + n.w);

        float4 rx = make_float4(px0 + ox.x, px1 + ox.y, px2 + ox.z, px3 + ox.w);
        float4 ry = make_float4(py0 + oy.x, py1 + oy.y, py2 + oy.z, py3 + oy.w);

        *reinterpret_cast<float4*>(out   + i) = rx;
        *reinterpret_cast<float4*>(out_y + i) = ry;
    } else {
        // Tail (num_pins not divisible by 4)
        for (int j = i; j < num_pins; ++j) {
            int n = p2n[j];
            out[j]   = __ldg(pos   + n) + offx[j];
            out_y[j] = __ldg(pos_y + n) + offy[j];
        }
    }
}

extern "C" void kernel_launch(void* const* d_in, const int* in_sizes, int n_in,
                              void* d_out, int out_size)
{
    // metadata order:
    // 0: pos (2*num_nodes float32)
    // 1: pin_offset_x (num_pins float32)
    // 2: pin_offset_y (num_pins float32)
    // 3: pin2node_map (num_pins int32 -- JAX x64 disabled)
    // 4: flat_node2pin_map (unused)
    // 5: flat_node2pin_start_map (unused)
    const float* pos  = (const float*)d_in[0];
    const float* offx = (const float*)d_in[1];
    const float* offy = (const float*)d_in[2];
    const int*   p2n  = (const int*)d_in[3];
    float* out = (float*)d_out;

    int num_nodes = in_sizes[0] / 2;
    int num_pins  = in_sizes[1];

    int threads = 256;
    int work = (num_pins + 3) / 4;                 // 4 pins per thread
    int blocks = (work + threads - 1) / threads;

    pinpos_kernel<<<blocks, threads>>>(pos, offx, offy, p2n, out,
                                       num_pins, num_nodes);
}

// round 12
// speedup vs baseline: 1.3668x; 1.3668x over previous
#include <cuda_runtime.h>
#include <stdint.h>

// PinPos forward: pin position = node position + pin offset (theta == 0).
// pos = [x_0..x_{N-1}, y_0..y_{N-1}]  (2N floats)
// out = [pinx_0..pinx_{P-1}, piny_0..piny_{P-1}]  (2P floats)
//
// R11 ncu: L1tex 83.5% (binding), L2 69.7%, DRAM 27.4%. Bottleneck is the
// 2x scattered 4B gathers per pin (16M L1tex wavefronts, 32B L2 sector each).
// Fix: pre-interleave pos into float2 posxy[N] so each pin needs ONE 8B
// gather (single sector, single wavefront) -> halves gather wavefronts and
// L2 gather traffic.

#define MAX_NODES 2000000

// Scratch: interleaved (x,y) per node. 16 MB static device array (allowed;
// no dynamic allocation).
__device__ float2 g_posxy[MAX_NODES];

__global__ __launch_bounds__(256)
void interleave_kernel(const float* __restrict__ pos, int num_nodes)
{
    const float* __restrict__ pos_y = pos + num_nodes;
    int i = (blockIdx.x * blockDim.x + threadIdx.x) * 4;

    if (i + 3 < num_nodes) {
        float4 x = *reinterpret_cast<const float4*>(pos + i);
        float4 y = *reinterpret_cast<const float4*>(pos_y + i);
        // two 16B stores (each = 2 float2)
        float4 lo = make_float4(x.x, y.x, x.y, y.y);
        float4 hi = make_float4(x.z, y.z, x.w, y.w);
        *reinterpret_cast<float4*>(&g_posxy[i])     = lo;
        *reinterpret_cast<float4*>(&g_posxy[i + 2]) = hi;
    } else {
        for (int j = i; j < num_nodes; ++j)
            g_posxy[j] = make_float2(pos[j], pos_y[j]);
    }
}

__global__ __launch_bounds__(256)
void pinpos_kernel(const float* __restrict__ offx,
                   const float* __restrict__ offy,
                   const int* __restrict__ p2n,
                   float* __restrict__ out,
                   int num_pins)
{
    float* __restrict__ out_y = out + num_pins;

    int i = (blockIdx.x * blockDim.x + threadIdx.x) * 4;

    if (i + 3 < num_pins) {
        // Front-batch streaming loads (3x16B) then 4 independent 8B gathers.
        float4 ox = *reinterpret_cast<const float4*>(offx + i);
        float4 oy = *reinterpret_cast<const float4*>(offy + i);
        int4   n  = *reinterpret_cast<const int4*>(p2n + i);

        float2 p0 = __ldg(&g_posxy[n.x]);
        float2 p1 = __ldg(&g_posxy[n.y]);
        float2 p2 = __ldg(&g_posxy[n.z]);
        float2 p3 = __ldg(&g_posxy[n.w]);

        float4 rx = make_float4(p0.x + ox.x, p1.x + ox.y, p2.x + ox.z, p3.x + ox.w);
        float4 ry = make_float4(p0.y + oy.x, p1.y + oy.y, p2.y + oy.z, p3.y + oy.w);

        *reinterpret_cast<float4*>(out   + i) = rx;
        *reinterpret_cast<float4*>(out_y + i) = ry;
    } else {
        for (int j = i; j < num_pins; ++j) {
            float2 p = __ldg(&g_posxy[p2n[j]]);
            out[j]   = p.x + offx[j];
            out_y[j] = p.y + offy[j];
        }
    }
}

extern "C" void kernel_launch(void* const* d_in, const int* in_sizes, int n_in,
                              void* d_out, int out_size)
{
    // metadata order:
    // 0: pos (2*num_nodes float32)
    // 1: pin_offset_x (num_pins float32)
    // 2: pin_offset_y (num_pins float32)
    // 3: pin2node_map (num_pins int32 -- JAX x64 disabled)
    // 4: flat_node2pin_map (unused)
    // 5: flat_node2pin_start_map (unused)
    const float* pos  = (const float*)d_in[0];
    const float* offx = (const float*)d_in[1];
    const float* offy = (const float*)d_in[2];
    const int*   p2n  = (const int*)d_in[3];
    float* out = (float*)d_out;

    int num_nodes = in_sizes[0] / 2;
    int num_pins  = in_sizes[1];

    const int threads = 256;

    int nwork = (num_nodes + 3) / 4;
    int nblocks = (nwork + threads - 1) / threads;
    interleave_kernel<<<nblocks, threads>>>(pos, num_nodes);

    int pwork = (num_pins + 3) / 4;
    int pblocks = (pwork + threads - 1) / threads;
    pinpos_kernel<<<pblocks, threads>>>(offx, offy, p2n, out, num_pins);
}